// round 6
// baseline (speedup 1.0000x reference)
#include <cuda_runtime.h>

#define Tlen  8192
#define Bsz   4
#define RES   256
#define SKIPC 512
#define NCLSC 256
#define NLAY  30
#define WIN   3072
#define HSTR  3200
#define KT    16
#define ASROW 640     // dup-padded row: 4 quarters x 8 groups x 20 floats

typedef unsigned long long ull;

// ---------------- device scratch (allocation-free) ----------------
__device__ float g_h[2][Bsz][RES][HSTR];          // ping-pong hidden state; pads zero
__device__ float g_WdT2[NLAY * 512 * ASROW];      // dup+skewed transposed conv weights
__device__ float g_WrT2[NLAY * 256 * ASROW];      // dup+skewed transposed residual weights
__device__ float g_gLast[NLAY][Bsz][RES];
__device__ float g_skip[Bsz][SKIPC];

// ---------------- helpers ----------------
__device__ __forceinline__ ull fma2(ull a, ull b, ull c) {
    ull d; asm("fma.rn.f32x2 %0, %1, %2, %3;" : "=l"(d) : "l"(a), "l"(b), "l"(c)); return d;
}
__device__ __forceinline__ float2 upk(ull v) {
    float2 f; asm("mov.b64 {%0,%1}, %2;" : "=f"(f.x), "=f"(f.y) : "l"(v)); return f;
}
__device__ __forceinline__ float gate_fn(float d) {
    float e1 = __expf(-d);
    float sg = __fdividef(1.f, 1.f + e1);
    float th = __fdividef(2.f, 1.f + e1 * e1) - 1.f;
    return th * sg;
}
__device__ __forceinline__ unsigned su32(const void* p) {
    return (unsigned)__cvta_generic_to_shared(p);
}

#define CPA16(d, s) asm volatile("cp.async.cg.shared.global [%0],[%1],16;\n" :: "r"(d), "l"(s))
#define CPA4(d, s)  asm volatile("cp.async.ca.shared.global [%0],[%1],4;\n"  :: "r"(d), "l"(s))
#define CPCOMMIT()  asm volatile("cp.async.commit_group;\n")
#define CPWAIT0()   asm volatile("cp.async.wait_group 0;\n" ::: "memory")

// ---------------- prep: transpose + duplicate + bank-skew weights ----------------
// dst[(lay*K + k)*ASROW + q*160 + cl*20 + 2*j {,+1}] = W[(lay*256 + co)*K + k],
// where co = q*64 + cl*8 + j.
__global__ void prep_dup(const float* __restrict__ W, float* __restrict__ dst, int K) {
    int k   = blockIdx.x;
    int lay = blockIdx.y;
    int co  = threadIdx.x;
    float v = W[((size_t)lay * 256 + co) * K + k];
    int q = co >> 6, cl = (co >> 3) & 7, j = co & 7;
    float* d = dst + ((size_t)lay * K + k) * ASROW + q * 160 + cl * 20 + 2 * j;
    d[0] = v; d[1] = v;
}

// ---------------- start conv ----------------
__global__ void start_conv(const float* __restrict__ x,
                           const float* __restrict__ Wst,
                           const float* __restrict__ bst) {
    int b = blockIdx.y;
    int u = blockIdx.x * 256 + threadIdx.x;
    int t = (Tlen - WIN) + u;
    float x0 = x[b * Tlen + t - 1];
    float x1 = x[b * Tlen + t];
    for (int c = 0; c < RES; c++)
        g_h[0][b][c][u] = bst[c] + Wst[2 * c] * x0 + Wst[2 * c + 1] * x1;
}

// ---------------- fused layer kernel ----------------
// Warp tile: 64 channels (cw quarter) x 4*NT columns (uw group).
// lane: cl = lane>>2 (8 channel-groups of 8), ul = lane&3 (4 column-subgroups of NT).
// A: dup pairs via 4x LDS.128, skewed -> 1 wf each. B: contiguous col pairs -> 1 wf.
template <int NT, int NUW>
__global__ void __launch_bounds__(128 * NUW, 1)
layer_kernel(int pp,
             const float* __restrict__ WA,  const float* __restrict__ bd,
             const float* __restrict__ WA2, const float* __restrict__ br,
             int dil, int u0, int layer) {
    constexpr int BN  = 4 * NT * NUW;
    constexpr int TPB = 128 * NUW;
    constexpr int NP  = NT / 2;

    extern __shared__ float smem[];
    float* As0 = smem;                                    // 2 x [KT][ASROW]
    float* Bs0 = smem + 2 * KT * ASROW;                   // 2 x [KT][BN]
    float* gs  = smem + 2 * KT * ASROW + 2 * KT * BN;     // [RES][BN]

    const int tid  = threadIdx.x;
    const int lane = tid & 31;
    const int w    = tid >> 5;
    const int cw   = w & 3;
    const int uw   = w >> 2;
    const int cl   = lane >> 2;
    const int ul   = lane & 3;
    const int chb  = cw * 64 + cl * 8;          // 8 channels chb..chb+7
    const int colb = uw * 4 * NT + ul * NT;     // NT columns colb..colb+NT-1
    const int b    = blockIdx.y;
    const int ub   = u0 + blockIdx.x * BN;

    const float* hin  = &g_h[pp][b][0][0];
    float*       hout = &g_h[pp ^ 1][b][0][0];

    ull acc[8][NP];
#pragma unroll
    for (int p = 0; p < 8; p++)
#pragma unroll
        for (int q = 0; q < NP; q++) acc[p][q] = 0ull;

    auto stageA = [&](int s, const float* src) {          // KT x ASROW contiguous
        float* dstb = As0 + s * KT * ASROW;
        for (int i = tid; i < KT * (ASROW / 4); i += TPB)
            CPA16(su32(dstb + 4 * i), src + 4 * i);
    };
    auto stageB = [&](int s, int k0) {
        float* dstb = Bs0 + s * KT * BN;
#pragma unroll
        for (int e = tid; e < KT * BN; e += TPB) {
            int kr = e / BN, u = e - kr * BN;
            int r  = k0 + kr;
            int ci = r >> 1;
            int off = (r & 1) ? 0 : dil;
            CPA4(su32(dstb + e), hin + ci * HSTR + (ub + u - off));
        }
    };

    auto compute = [&](const float* A, const float* B) {
#pragma unroll
        for (int kk = 0; kk < KT; kk++) {
            const float* ar = A + kk * ASROW + cw * 160 + cl * 20;
            ulonglong2 t0 = *(const ulonglong2*)(ar);
            ulonglong2 t1 = *(const ulonglong2*)(ar + 4);
            ulonglong2 t2 = *(const ulonglong2*)(ar + 8);
            ulonglong2 t3 = *(const ulonglong2*)(ar + 12);
            ull a2[8] = {t0.x, t0.y, t1.x, t1.y, t2.x, t2.y, t3.x, t3.y};
            ull b2[NP];
            const float* bp = B + kk * BN + colb;
            if (NT == 8) {
                ulonglong2 u0v = *(const ulonglong2*)(bp);
                ulonglong2 u1v = *(const ulonglong2*)(bp + 4);
                b2[0] = u0v.x; b2[1] = u0v.y; b2[2] = u1v.x; b2[3] = u1v.y;
            } else if (NT == 4) {
                ulonglong2 u0v = *(const ulonglong2*)(bp);
                b2[0] = u0v.x; b2[1] = u0v.y;
            } else {
                b2[0] = *(const ull*)(bp);
            }
#pragma unroll
            for (int p = 0; p < 8; p++)
#pragma unroll
                for (int q = 0; q < NP; q++) acc[p][q] = fma2(a2[p], b2[q], acc[p][q]);
        }
    };

    // ---- phase 1: dilated conv, K = 512 (32 tiles of KT=16) ----
    stageA(0, WA); stageB(0, 0); CPCOMMIT();
    int cur = 0;
    for (int t = 0; t < 32; t++) {
        CPWAIT0(); __syncthreads();
        if (t + 1 < 32) { stageA(cur ^ 1, WA + (size_t)(t + 1) * KT * ASROW); stageB(cur ^ 1, (t + 1) * KT); }
        else            { stageA(cur ^ 1, WA2); }   // prefetch phase-2 tile 0
        CPCOMMIT();
        compute(As0 + cur * KT * ASROW, Bs0 + cur * KT * BN);
        cur ^= 1;
    }

    // ---- gate -> gs, extract t = T-1 column, reset acc ----
#pragma unroll
    for (int p = 0; p < 8; p++) {
        int co = chb + p;
        float bdv = bd[co];
#pragma unroll
        for (int q = 0; q < NP; q++) {
            float2 v = upk(acc[p][q]);
            float g0 = gate_fn(v.x + bdv);
            float g1 = gate_fn(v.y + bdv);
            int col = colb + 2 * q;
            gs[co * BN + col]     = g0;
            gs[co * BN + col + 1] = g1;
            int uu = ub + col;
            if (uu == WIN - 1)     g_gLast[layer][b][co] = g0;
            if (uu + 1 == WIN - 1) g_gLast[layer][b][co] = g1;
            acc[p][q] = 0ull;
        }
    }

    // ---- phase 2: residual GEMM, K = 256 (16 tiles), B = gs ----
    for (int t = 0; t < 16; t++) {
        CPWAIT0(); __syncthreads();    // publishes gs before first read
        if (t + 1 < 16) stageA(cur ^ 1, WA2 + (size_t)(t + 1) * KT * ASROW);
        CPCOMMIT();
        compute(As0 + cur * KT * ASROW, gs + t * KT * BN);
        cur ^= 1;
    }

    // ---- residual epilogue ----
#pragma unroll
    for (int p = 0; p < 8; p++) {
        int co = chb + p;
        float brv = br[co];
#pragma unroll
        for (int q = 0; q < NP; q++) {
            float2 v = upk(acc[p][q]);
            int uu = ub + colb + 2 * q;
            if (uu < WIN)     hout[co * HSTR + uu]     = hin[co * HSTR + uu]     + v.x + brv;
            if (uu + 1 < WIN) hout[co * HSTR + uu + 1] = hin[co * HSTR + uu + 1] + v.y + brv;
        }
    }
}

// ---------------- skip head ----------------
__global__ void skip_kernel(const float* __restrict__ Ws, const float* __restrict__ bs) {
    int b = blockIdx.x;
    int w = threadIdx.x >> 5;
    int lane = threadIdx.x & 31;
    int so_base = blockIdx.y * 64 + w * 8;
    for (int oi = 0; oi < 8; oi++) {
        int so = so_base + oi;
        float v = (lane < NLAY) ? bs[lane * SKIPC + so] : 0.f;
        for (int l = 0; l < NLAY; l++) {
            const float* wr = Ws + ((size_t)l * SKIPC + so) * RES;
            const float* gg = &g_gLast[l][b][0];
#pragma unroll
            for (int k = lane; k < RES; k += 32) v += wr[k] * gg[k];
        }
#pragma unroll
        for (int s = 16; s; s >>= 1) v += __shfl_xor_sync(0xffffffffu, v, s);
        if (lane == 0) g_skip[b][so] = fmaxf(v, 0.f);
    }
}

// ---------------- end head ----------------
__global__ void end_kernel(const float* __restrict__ We1, const float* __restrict__ be1,
                           const float* __restrict__ We2, const float* __restrict__ be2,
                           float* __restrict__ out) {
    __shared__ float sk[SKIPC];
    __shared__ float mid[SKIPC];
    int b = blockIdx.x;
    int tid = threadIdx.x;
    int w = tid >> 5, lane = tid & 31;
    for (int i = tid; i < SKIPC; i += 256) sk[i] = g_skip[b][i];
    __syncthreads();
    for (int oi = 0; oi < 64; oi++) {
        int so = w * 64 + oi;
        const float* row = We1 + (size_t)so * SKIPC;
        float v = 0.f;
#pragma unroll
        for (int k = lane; k < SKIPC; k += 32) v += row[k] * sk[k];
#pragma unroll
        for (int s = 16; s; s >>= 1) v += __shfl_xor_sync(0xffffffffu, v, s);
        if (lane == 0) mid[so] = fmaxf(v + be1[so], 0.f);
    }
    __syncthreads();
    for (int oi = 0; oi < 32; oi++) {
        int nc = w * 32 + oi;
        const float* row = We2 + (size_t)nc * SKIPC;
        float v = 0.f;
#pragma unroll
        for (int k = lane; k < SKIPC; k += 32) v += row[k] * mid[k];
#pragma unroll
        for (int s = 16; s; s >>= 1) v += __shfl_xor_sync(0xffffffffu, v, s);
        if (lane == 0) out[b * NCLSC + nc] = v + be2[nc];
    }
}

// ---------------- host ----------------
static const int DILS[NLAY] = {1,2,4,8,16,32,64,128,256,512,
                               1,2,4,8,16,32,64,128,256,512,
                               1,2,4,8,16,32,64,128,256,512};

static inline size_t smem_for(int BN) {
    return (size_t)(2 * KT * ASROW + 2 * KT * BN + RES * BN) * sizeof(float);
}

extern "C" void kernel_launch(void* const* d_in, const int* in_sizes, int n_in,
                              void* d_out, int out_size) {
    (void)in_sizes; (void)n_in; (void)out_size;
    const float* x   = (const float*)d_in[0];
    const float* Wst = (const float*)d_in[1];
    const float* bst = (const float*)d_in[2];
    const float* Wd  = (const float*)d_in[3];
    const float* bd  = (const float*)d_in[4];
    const float* Wr  = (const float*)d_in[5];
    const float* br  = (const float*)d_in[6];
    const float* Ws  = (const float*)d_in[7];
    const float* bs  = (const float*)d_in[8];
    const float* We1 = (const float*)d_in[9];
    const float* be1 = (const float*)d_in[10];
    const float* We2 = (const float*)d_in[11];
    const float* be2 = (const float*)d_in[12];
    float* out = (float*)d_out;

    cudaFuncSetAttribute((const void*)layer_kernel<8, 3>, cudaFuncAttributeMaxDynamicSharedMemorySize, (int)smem_for(96));
    cudaFuncSetAttribute((const void*)layer_kernel<4, 4>, cudaFuncAttributeMaxDynamicSharedMemorySize, (int)smem_for(64));
    cudaFuncSetAttribute((const void*)layer_kernel<2, 4>, cudaFuncAttributeMaxDynamicSharedMemorySize, (int)smem_for(32));
    cudaFuncSetAttribute((const void*)layer_kernel<2, 2>, cudaFuncAttributeMaxDynamicSharedMemorySize, (int)smem_for(16));

    float* wdT_dev; float* wrT_dev;
    cudaGetSymbolAddress((void**)&wdT_dev, g_WdT2);
    cudaGetSymbolAddress((void**)&wrT_dev, g_WrT2);

    prep_dup<<<dim3(512, NLAY), 256>>>(Wd, wdT_dev, 512);
    prep_dup<<<dim3(256, NLAY), 256>>>(Wr, wrT_dev, 256);
    start_conv<<<dim3(WIN / 256, Bsz), 256>>>(x, Wst, bst);

    int suf[NLAY + 1];
    suf[NLAY] = 0;
    for (int i = NLAY - 1; i >= 0; i--) suf[i] = suf[i + 1] + DILS[i];

    for (int i = 0; i < NLAY; i++) {
        int N  = 1 + suf[i + 1];
        int u0 = WIN - N;
        int pp = i & 1;
        const float* bdp   = bd + (size_t)i * RES;
        const float* brp   = br + (size_t)i * RES;
        const float* wdt_l = wdT_dev + (size_t)i * 512 * ASROW;
        const float* wrt_l = wrT_dev + (size_t)i * 256 * ASROW;

        int BN = (N > 64 * 37) ? 96 : (N > 32 * 37) ? 64 : (N > 16 * 37) ? 32 : 16;
        int gx = (N + BN - 1) / BN;
        dim3 grid(gx, Bsz);
        size_t sm = smem_for(BN);
        switch (BN) {
            case 96: layer_kernel<8, 3><<<grid, 384, sm>>>(pp, wdt_l, bdp, wrt_l, brp, DILS[i], u0, i); break;
            case 64: layer_kernel<4, 4><<<grid, 512, sm>>>(pp, wdt_l, bdp, wrt_l, brp, DILS[i], u0, i); break;
            case 32: layer_kernel<2, 4><<<grid, 512, sm>>>(pp, wdt_l, bdp, wrt_l, brp, DILS[i], u0, i); break;
            default: layer_kernel<2, 2><<<grid, 256, sm>>>(pp, wdt_l, bdp, wrt_l, brp, DILS[i], u0, i); break;
        }
    }

    skip_kernel<<<dim3(Bsz, SKIPC / 64), 256>>>(Ws, bs);
    end_kernel<<<Bsz, 256>>>(We1, be1, We2, be2, out);
}